// round 6
// baseline (speedup 1.0000x reference)
#include <cuda_runtime.h>
#include <cuda_fp16.h>
#include <cstdint>
#include <math.h>

#define Bk 8
#define Lk 2048
#define Dk 2048
#define Rk 256
#define BLk (Bk * Lk)   // 16384 rows

// ---------------- device scratch ----------------
static __device__ float g_C[Rk * Rk];                 // Toeplitz matrix C[s,i]
static __device__ float g_E[Rk * Rk];                 // E = C @ dlt       (256x256)
static __device__ __half g_BT1[Rk * Dk];              // A'^T fp16         (256x2048)
static __device__ __half g_WqT[Dk * Rk];              // Wq^T fp16         (2048x256)
static __device__ __half g_U[(size_t)BLk * Rk];       // z_mixed fp16
static __device__ float g_feat[BLk];
static __device__ float g_pg[Rk], g_pb[Rk];
static __device__ float g_cA[Rk], g_cB[Rk];
static __device__ float g_G[Dk];
static __device__ float g_consts[4];
static __device__ float g_pgp[32 * Rk], g_pbp[32 * Rk];

// ---------------- helpers ----------------
__device__ __forceinline__ uint32_t smem_u32(const void* p) {
    uint32_t a;
    asm("{ .reg .u64 t; cvta.to.shared.u64 t, %1; cvt.u32.u64 %0, t; }" : "=r"(a) : "l"(p));
    return a;
}
__device__ __forceinline__ void cp16(void* dst, const void* src) {
    uint32_t d = smem_u32(dst);
    asm volatile("cp.async.cg.shared.global [%0], [%1], 16;" :: "r"(d), "l"(src) : "memory");
}
#define CP_COMMIT() asm volatile("cp.async.commit_group;" ::: "memory")
#define CP_WAIT0()  asm volatile("cp.async.wait_group 0;" ::: "memory")
#define CP_WAIT1()  asm volatile("cp.async.wait_group 1;" ::: "memory")

#define LDSM4(r0, r1, r2, r3, addr) \
    asm volatile("ldmatrix.sync.aligned.m8n8.x4.shared.b16 {%0,%1,%2,%3}, [%4];" \
        : "=r"(r0), "=r"(r1), "=r"(r2), "=r"(r3) : "r"(addr))

#define MMAF16(c, a, b) \
    asm volatile( \
        "mma.sync.aligned.m16n8k16.row.col.f32.f16.f16.f32 " \
        "{%0,%1,%2,%3},{%4,%5,%6,%7},{%8,%9},{%0,%1,%2,%3};" \
        : "+f"((c)[0]), "+f"((c)[1]), "+f"((c)[2]), "+f"((c)[3]) \
        : "r"((a)[0]), "r"((a)[1]), "r"((a)[2]), "r"((a)[3]), \
          "r"((b)[0]), "r"((b)[1]))

__device__ __forceinline__ uint32_t h2pack(float a, float b) {
    __half2 h = __floats2half2_rn(a, b);
    return *reinterpret_cast<uint32_t*>(&h);
}

__device__ __forceinline__ float blockReduce256(float v, float* sm) {
    int t = threadIdx.x;
    sm[t] = v;
    __syncthreads();
    #pragma unroll
    for (int off = 128; off > 0; off >>= 1) {
        if (t < off) sm[t] += sm[t + off];
        __syncthreads();
    }
    float r = sm[0];
    __syncthreads();
    return r;
}

// pad-40-halves row layout (80 bytes): ldmatrix phases conflict-free.
#define PADH 40
#define PADB 80

// ================= fused precompute 1 =================
// bid 0: consts; 1..32: pgb partials; 33..288: build C; 289..800: WqT transpose
__global__ __launch_bounds__(256) void kPre1(const float* __restrict__ gamma,
                                             const float* __restrict__ beta,
                                             const float* __restrict__ phiw,
                                             const float* __restrict__ P,
                                             const float* __restrict__ toep,
                                             const float* __restrict__ Wq, int Kc) {
    int bid = blockIdx.x, t = threadIdx.x;
    if (bid == 0) {
        __shared__ float sm[256];
        float a = 0.f, b = 0.f, c = 0.f;
        for (int j = t; j < Dk; j += 256) { a += gamma[j]; b += beta[j]; }
        for (int j = t; j < Rk; j += 256) { c += phiw[j]; }
        float A = blockReduce256(a, sm);
        float B = blockReduce256(b, sm);
        float C = blockReduce256(c, sm);
        if (t == 0) { g_consts[0] = A; g_consts[1] = B; g_consts[2] = C; }
    } else if (bid <= 32) {
        int chunk = bid - 1;
        float ag = 0.f, ab = 0.f;
        #pragma unroll 4
        for (int j = 0; j < 64; j++) {
            int d = chunk * 64 + j;
            float p = P[(size_t)d * Rk + t];
            ag += gamma[d] * p;
            ab += beta[d] * p;
        }
        g_pgp[chunk * Rk + t] = ag;
        g_pbp[chunk * Rk + t] = ab;
    } else if (bid <= 288) {
        int s = bid - 33;
        int pad = (Kc - 1) >> 1;
        int idx = t - s + pad;
        g_C[s * Rk + t] = (idx >= 0 && idx < Kc) ? toep[idx] : 0.f;
    } else {
        int id = bid - 289;
        int bx = id & 63, by = id >> 6;
        __shared__ float tile[32][33];
        int tx = t & 31, ty8 = t >> 5;
        #pragma unroll
        for (int i = 0; i < 32; i += 8)
            tile[ty8 + i][tx] = Wq[(size_t)(by * 32 + ty8 + i) * Dk + bx * 32 + tx];
        __syncthreads();
        #pragma unroll
        for (int i = 0; i < 32; i += 8)
            g_WqT[(size_t)(bx * 32 + ty8 + i) * Rk + by * 32 + tx] =
                __float2half_rn(tile[tx][ty8 + i]);
    }
}

// ================= kEg: E = C @ dlt (fp32 64x64 tiles) + pgb2 reduce =================
__global__ __launch_bounds__(256) void kEg(const float* __restrict__ dlt) {
    int bid = blockIdx.x, t = threadIdx.x;
    if (bid == 16) {  // pgb2
        float a = 0.f, b = 0.f;
        #pragma unroll
        for (int c = 0; c < 32; c++) { a += g_pgp[c * Rk + t]; b += g_pbp[c * Rk + t]; }
        g_pg[t] = a;
        g_pb[t] = b;
        return;
    }
    __shared__ float Cs[16][66];
    __shared__ float Ds[16][68];
    int bx = bid & 3, by = bid >> 2;
    int sBase = by * 64, rBase = bx * 64;
    int ty = t >> 4, tx = t & 15;
    float acc[4][4] = {};
    for (int k0 = 0; k0 < Rk; k0 += 16) {
        {
            int m = t >> 2, kq = (t & 3) * 4;
            float4 v = *(const float4*)&g_C[(size_t)(sBase + m) * Rk + k0 + kq];
            Cs[kq + 0][m] = v.x; Cs[kq + 1][m] = v.y; Cs[kq + 2][m] = v.z; Cs[kq + 3][m] = v.w;
        }
        {
            int kk = t >> 4, n4 = (t & 15) * 4;
            float4 v = *(const float4*)&dlt[(size_t)(k0 + kk) * Rk + rBase + n4];
            *(float4*)&Ds[kk][n4] = v;
        }
        __syncthreads();
        #pragma unroll
        for (int k = 0; k < 16; k++) {
            float a[4], b[4];
            #pragma unroll
            for (int i = 0; i < 4; i++) a[i] = Cs[k][ty * 4 + i];
            #pragma unroll
            for (int j = 0; j < 4; j++) b[j] = Ds[k][tx * 4 + j];
            #pragma unroll
            for (int i = 0; i < 4; i++)
                #pragma unroll
                for (int j = 0; j < 4; j++) acc[i][j] += a[i] * b[j];
        }
        __syncthreads();
    }
    #pragma unroll
    for (int i = 0; i < 4; i++)
        #pragma unroll
        for (int j = 0; j < 4; j++)
            g_E[(size_t)(sBase + ty * 4 + i) * Rk + rBase + tx * 4 + j] = acc[i][j];
}

// ================= kApCab: A'^T (fp16) + cA/cB =================
__global__ __launch_bounds__(256) void kApCab(const float* __restrict__ P,
                                              const float* __restrict__ gamma) {
    int bid = blockIdx.x, t = threadIdx.x;
    if (bid >= 128) {
        __shared__ float sm[256];
        int s = bid - 128;
        float e = g_E[(size_t)s * Rk + t];
        float ca = blockReduce256(g_pg[t] * e, sm);
        float cb = blockReduce256(g_pb[t] * e, sm);
        if (t == 0) { g_cA[s] = ca; g_cB[s] = cb; }
        return;
    }
    __shared__ float Ps[16][64];
    __shared__ float Es[16][64];
    int bx = bid & 3, by = bid >> 2;
    int dBase = by * 64, sBase = bx * 64;
    int ty = t >> 4, tx = t & 15;
    float acc[4][4] = {};
    for (int k0 = 0; k0 < Rk; k0 += 16) {
        {
            int m = t >> 2, kq = (t & 3) * 4;
            float4 v = *(const float4*)&P[(size_t)(dBase + m) * Rk + k0 + kq];
            Ps[kq + 0][m] = v.x; Ps[kq + 1][m] = v.y; Ps[kq + 2][m] = v.z; Ps[kq + 3][m] = v.w;
        }
        {
            int n = t >> 2, kq = (t & 3) * 4;
            float4 v = *(const float4*)&g_E[(size_t)(sBase + n) * Rk + k0 + kq];
            Es[kq + 0][n] = v.x; Es[kq + 1][n] = v.y; Es[kq + 2][n] = v.z; Es[kq + 3][n] = v.w;
        }
        __syncthreads();
        #pragma unroll
        for (int k = 0; k < 16; k++) {
            float a[4], b[4];
            #pragma unroll
            for (int i = 0; i < 4; i++) a[i] = Ps[k][ty * 4 + i];
            #pragma unroll
            for (int j = 0; j < 4; j++) b[j] = Es[k][tx * 4 + j];
            #pragma unroll
            for (int i = 0; i < 4; i++)
                #pragma unroll
                for (int j = 0; j < 4; j++) acc[i][j] += a[i] * b[j];
        }
        __syncthreads();
    }
    #pragma unroll
    for (int i = 0; i < 4; i++) {
        int d = dBase + ty * 4 + i;
        float g = gamma[d];
        #pragma unroll
        for (int j = 0; j < 4; j++) {
            int s = sBase + tx * 4 + j;
            g_BT1[(size_t)s * Dk + d] = __float2half_rn(g * acc[i][j]);
        }
    }
}

// G[l] = sigmoid(g_logit[..]) * scale[l]
__global__ void kScale(const float* __restrict__ phib, const float* __restrict__ glog,
                       const int* __restrict__ step_p, int glen) {
    int w = threadIdx.x >> 5, lane = threadIdx.x & 31;
    int l = blockIdx.x * 8 + w;
    const float PI_F = 3.14159274101257324f;
    float base = PI_F * ((float)l + 0.5f);
    float c1 = 0.f, c2 = 0.f;
    #pragma unroll
    for (int j = 0; j < 8; j++) {
        int r = lane + 32 * j;
        c1 += cosf((base * (float)r) / (float)Lk);
        c2 += phib[(size_t)l * Rk + r];
    }
    float c3 = (lane < Bk) ? g_feat[(size_t)lane * Lk + l] : 0.f;
    #pragma unroll
    for (int o = 16; o > 0; o >>= 1) {
        c1 += __shfl_xor_sync(0xffffffffu, c1, o);
        c2 += __shfl_xor_sync(0xffffffffu, c2, o);
        c3 += __shfl_xor_sync(0xffffffffu, c3, o);
    }
    if (lane == 0) {
        int step = *step_p;
        float det_scale = fminf((float)((double)step / 2000.0), 1.0f);
        float scale = det_scale * (c1 / (float)Rk) + (c2 / (float)Rk)
                    + (c3 / (float)Bk) * (g_consts[2] / (float)Rk);
        int gi = l / (Dk / glen);
        float gs = 1.0f / (1.0f + expf(-glog[gi]));
        g_G[l] = gs * scale;
    }
}

// ================= fp16 mma GEMM 1 =================
// U = (X @ A')*rstd + nmr*cA + cB; M=16384, N=256, K=2048. BK=32, NT=64.
// grid 256 CTAs (tile 64x256), 256 thr (8 warps, warp tile 32x64), 2 CTAs/SM.
// 3-stage pipeline: A via LDG->regs->STS (distance 2), B via cp.async (wait_group 1).
#define NT1 64
#define SM1_AS   0        // 3 stages x 5120 B (64 rows x 80 B)
#define SM1_AST  5120
#define SM1_BS   15360    // 3 stages x 20480 B (256 rows x 80 B)
#define SM1_BST  20480
#define SM1_GAM  76800
#define SM1_RSTD 84992
#define SM1_NMR  85248
#define SM1_TOTAL 85504

__global__ __launch_bounds__(256, 2) void kGemm1MMA(const float* __restrict__ X,
                                                    const float* __restrict__ gamma) {
    extern __shared__ char sm1[];
    float* s_gam  = (float*)(sm1 + SM1_GAM);
    float* s_rstd = (float*)(sm1 + SM1_RSTD);
    float* s_nmr  = (float*)(sm1 + SM1_NMR);

    int t = threadIdx.x, w = t >> 5, lane = t & 31, g = lane >> 2, tg = lane & 3;
    int rowBase = blockIdx.x * 64;
    int m0w = (w & 1) * 32, n0w = (w >> 1) * 64;

    for (int i = t; i < Dk / 4; i += 256)
        ((float4*)s_gam)[i] = ((const float4*)gamma)[i];

    uint32_t sBase = smem_u32(sm1);
    uint32_t aBase = (uint32_t)((m0w + (lane & 15)) * PADB + (lane >> 4) * 16);
    uint32_t bBase = (uint32_t)((n0w + (lane & 7) + ((lane >> 4) << 3)) * PADB
                                + ((lane >> 3) & 1) * 16);

    int lr = t >> 2, h = t & 3;   // A staging: row (0..63), 8-float chunk (0..3)
    const float4* Xr = (const float4*)(X + (size_t)(rowBase + lr) * Dk);
    const __half* Bsrc = g_BT1 + (size_t)t * Dk;   // B staging: one col-row per thread

    float acc[2][8][4] = {};
    float s0 = 0.f, s20 = 0.f, sg0 = 0.f;

    __syncthreads();  // gamma visible

    // ---- A process: stats + pack + STS for tile tt into stage st ----
    #define G1_APROC(st, tt, q0, q1) do { \
        float4 gv0 = ((const float4*)s_gam)[(tt) * 8 + h * 2]; \
        float4 gv1 = ((const float4*)s_gam)[(tt) * 8 + h * 2 + 1]; \
        s0  += (q0.x + q0.y) + (q0.z + q0.w) + (q1.x + q1.y) + (q1.z + q1.w); \
        s20 += q0.x*q0.x + q0.y*q0.y + q0.z*q0.z + q0.w*q0.w \
             + q1.x*q1.x + q1.y*q1.y + q1.z*q1.z + q1.w*q1.w; \
        sg0 += gv0.x*q0.x + gv0.y*q0.y + gv0.z*q0.z + gv0.w*q0.w \
             + gv1.x*q1.x + gv1.y*q1.y + gv1.z*q1.z + gv1.w*q1.w; \
        uint4 pk = { h2pack(q0.x, q0.y), h2pack(q0.z, q0.w), \
                     h2pack(q1.x, q1.y), h2pack(q1.z, q1.w) }; \
        *(uint4*)((__half*)(sm1 + SM1_AS + (st) * SM1_AST) + lr * PADH + h * 8) = pk; \
    } while (0)

    #define G1_BISSUE(st, tt) do { \
        __half* B = (__half*)(sm1 + SM1_BS + (st) * SM1_BST); \
        const __half* src = Bsrc + (tt) * 32; \
        cp16(B + t * PADH + 0,  src); \
        cp16(B + t * PADH + 8,  src + 8); \
        cp16(B + t * PADH + 16, src + 16); \
        cp16(B + t * PADH + 24, src + 24); \
        CP_COMMIT(); \
    } while (0)

    // prologue: stages 0 and 1
    {
        float4 q0 = Xr[h * 2], q1 = Xr[h * 2 + 1];
        G1_APROC(0, 0, q0, q1);
        G1_BISSUE(0, 0);
        q0 = Xr[8 + h * 2]; q1 = Xr[8 + h * 2 + 1];
        G1_APROC(1, 1, q0, q1);
        G1_BISSUE(1, 1);
    }
    CP_WAIT1();
    __syncthreads();

    #pragma unroll 1
    for (int tt = 0; tt < NT1; ++tt) {
        float4 q0, q1;
        if (tt + 2 < NT1) {   // issue LDG early: latency spans the compute below
            q0 = Xr[(tt + 2) * 8 + h * 2];
            q1 = Xr[(tt + 2) * 8 + h * 2 + 1];
        }
        // compute stage tt%3
        {
            uint32_t sA = sBase + SM1_AS + (tt % 3) * SM1_AST;
            uint32_t sB = sBase + SM1_BS + (tt % 3) * SM1_BST;
            #pragma unroll
            for (int ks = 0; ks < 2; ++ks) {
                uint32_t af[2][4], bf[8][2];
                #pragma unroll
                for (int mi = 0; mi < 2; ++mi)
                    LDSM4(af[mi][0], af[mi][1], af[mi][2], af[mi][3],
                          sA + aBase + mi * 16 * PADB + ks * 32);
                #pragma unroll
                for (int ni2 = 0; ni2 < 4; ++ni2) {
                    uint32_t r0, r1, r2, r3;
                    LDSM4(r0, r1, r2, r3, sB + bBase + ni2 * 16 * PADB + ks * 32);
                    bf[ni2 * 2][0] = r0; bf[ni2 * 2][1] = r1;
                    bf[ni2 * 2 + 1][0] = r2; bf[ni2 * 2 + 1][1] = r3;
                }
                #pragma unroll
                for (int mi = 0; mi < 2; ++mi)
                    #pragma unroll
                    for (int ni = 0; ni < 8; ++ni)
                        MMAF16(acc[mi][ni], af[mi], bf[ni]);
            }
        }
        if (tt + 2 < NT1) {
            int st = (tt + 2) % 3;
            G1_APROC(st, tt + 2, q0, q1);
            G1_BISSUE(st, tt + 2);
            CP_WAIT1();
        } else if (tt + 1 < NT1) {
            CP_WAIT0();
        }
        __syncthreads();
    }

    // LN stats: 4 staging threads per row (h = 0..3, consecutive lanes)
    #pragma unroll
    for (int o = 1; o <= 2; o <<= 1) {
        s0  += __shfl_xor_sync(0xffffffffu, s0, o);
        s20 += __shfl_xor_sync(0xffffffffu, s20, o);
        sg0 += __shfl_xor_sync(0xffffffffu, sg0, o);
    }
    if (h == 0) {
        float C0 = g_consts[0], C1 = g_consts[1];
        float mean = s0 * (1.f / Dk);
        float var = s20 * (1.f / Dk) - mean * mean;
        float rstd = rsqrtf(var + 1e-5f);
        s_rstd[lr] = rstd;
        s_nmr[lr] = -mean * rstd;
        g_feat[rowBase + lr] = (sg0 - mean * C0) * rstd * (1.f / Dk) + C1 * (1.f / Dk);
    }
    __syncthreads();

    // epilogue -> g_U (fp16)
    #pragma unroll
    for (int ni = 0; ni < 8; ++ni) {
        int cg = n0w + ni * 8 + 2 * tg;
        float ca0 = g_cA[cg], ca1 = g_cA[cg + 1];
        float cb0 = g_cB[cg], cb1 = g_cB[cg + 1];
        #pragma unroll
        for (int mi = 0; mi < 2; ++mi) {
            int r1 = m0w + mi * 16 + g;
            float rs1 = s_rstd[r1], nm1 = s_nmr[r1];
            float rs2 = s_rstd[r1 + 8], nm2 = s_nmr[r1 + 8];
            uint32_t o1 = h2pack(acc[mi][ni][0] * rs1 + nm1 * ca0 + cb0,
                                 acc[mi][ni][1] * rs1 + nm1 * ca1 + cb1);
            uint32_t o2 = h2pack(acc[mi][ni][2] * rs2 + nm2 * ca0 + cb0,
                                 acc[mi][ni][3] * rs2 + nm2 * ca1 + cb1);
            *(uint32_t*)(g_U + (size_t)(rowBase + r1) * Rk + cg) = o1;
            *(uint32_t*)(g_U + (size_t)(rowBase + r1 + 8) * Rk + cg) = o2;
        }
    }
}

// ================= fp16 mma GEMM 2 =================
// out = G[d]*(U @ Wq + bq); M=16384, N=2048, K=256. grid (16,128), 256 thr,
// CTA tile 128x128, warp tile 64x32, BK=32, NT=8, 3-stage cp.async pipeline.
#define NT2 8
#define SM2_STAGE 20480   // bytes per stage (A 10240 + B 10240)
#define SM2_TOTAL 61440

__global__ __launch_bounds__(256) void kGemm2MMA(const float* __restrict__ bq,
                                                 float* __restrict__ out) {
    extern __shared__ char sm2[];
    int t = threadIdx.x, w = t >> 5, lane = t & 31, g = lane >> 2, tg = lane & 3;
    int rowBase = blockIdx.y * 128, colBase = blockIdx.x * 128;
    int m0w = (w >> 2) * 64, n0w = (w & 3) * 32;

    uint32_t sBase0 = smem_u32(sm2);
    uint32_t aBase = (uint32_t)((m0w + (lane & 15)) * PADB + (lane >> 4) * 16);
    uint32_t bBase = 10240u + (uint32_t)((n0w + (lane & 7) + ((lane >> 4) << 3)) * PADB
                                         + ((lane >> 3) & 1) * 16);

    int lr = t >> 1, h = t & 1;
    const __half* Asrc = g_U + (size_t)(rowBase + lr) * Rk + h * 16;
    const __half* Bsrc = g_WqT + (size_t)(colBase + lr) * Rk + h * 16;

    float acc[4][4][4] = {};

    #define G2_ISSUE(st, tt) do { \
        __half* A = (__half*)(sm2 + (st) * SM2_STAGE); \
        __half* B = (__half*)(sm2 + (st) * SM2_STAGE + 10240); \
        cp16(A + lr * PADH + h * 16,     Asrc + (tt) * 32); \
        cp16(A + lr * PADH + h * 16 + 8, Asrc + (tt) * 32 + 8); \
        cp16(B + lr * PADH + h * 16,     Bsrc + (tt) * 32); \
        cp16(B + lr * PADH + h * 16 + 8, Bsrc + (tt) * 32 + 8); \
        CP_COMMIT(); \
    } while (0)

    G2_ISSUE(0, 0);
    G2_ISSUE(1, 1);
    CP_WAIT1();
    __syncthreads();

    #pragma unroll 1
    for (int tt = 0; tt < NT2; ++tt) {
        int st = tt % 3;
        uint32_t sb = sBase0 + st * SM2_STAGE;
        #pragma unroll
        for (int ks = 0; ks < 2; ++ks) {
            uint32_t af[4][4], bf[4][2];
            #pragma unroll
            for (int mi = 0; mi < 4; ++mi)
                LDSM4(af[mi][0], af[mi][1], af[mi][2], af[mi][3],
                      sb + aBase + mi * 16 * PADB + ks * 32);
            #pragma unroll
            for (int ni2 = 0; ni2 < 2; ++ni2) {
                uint32_t r0, r1, r2, r3;
                LDSM4(r0, r1, r2, r3, sb + bBase + ni2 * 16 * PADB + ks * 32);
                bf[ni2 * 2][0] = r0; bf[ni2 * 2][1] = r1;
                bf[ni2 * 2 + 1][0] = r2; bf[ni2 * 2 + 1][1] = r3;
            }
            #pragma unroll
            for (int mi = 0; mi < 4; ++mi)
                #pragma unroll
                for (int ni = 0; ni < 4; ++ni)
                    MMAF16(acc[mi][ni], af[mi], bf[ni]);
        }
        if (tt + 2 < NT2) {
            G2_ISSUE((tt + 2) % 3, tt + 2);
            CP_WAIT1();
        } else if (tt + 1 < NT2) {
            CP_WAIT0();
        }
        __syncthreads();
    }

    #pragma unroll
    for (int ni = 0; ni < 4; ++ni) {
        int cg = colBase + n0w + ni * 8 + 2 * tg;
        float G0 = g_G[cg], G1 = g_G[cg + 1];
        float q0 = bq[cg], q1 = bq[cg + 1];
        #pragma unroll
        for (int mi = 0; mi < 4; ++mi) {
            int r1 = rowBase + m0w + mi * 16 + g;
            float2 o1, o2;
            o1.x = G0 * (acc[mi][ni][0] + q0);
            o1.y = G1 * (acc[mi][ni][1] + q1);
            o2.x = G0 * (acc[mi][ni][2] + q0);
            o2.y = G1 * (acc[mi][ni][3] + q1);
            *(float2*)&out[(size_t)r1 * Dk + cg] = o1;
            *(float2*)&out[(size_t)(r1 + 8) * Dk + cg] = o2;
        }
    }
}

// ---------------- launch ----------------
extern "C" void kernel_launch(void* const* d_in, const int* in_sizes, int n_in,
                              void* d_out, int out_size) {
    const float* x     = (const float*)d_in[0];
    const float* gamma = (const float*)d_in[1];
    const float* beta  = (const float*)d_in[2];
    const float* P     = (const float*)d_in[3];
    const float* dlt   = (const float*)d_in[4];
    const float* phiw  = (const float*)d_in[5];
    const float* phib  = (const float*)d_in[6];
    const float* toep  = (const float*)d_in[7];
    const float* Wq    = (const float*)d_in[8];
    const float* bq    = (const float*)d_in[9];
    const float* glog  = (const float*)d_in[10];
    const int*   step  = (const int*)d_in[11];
    int Kc   = in_sizes[7];
    int glen = in_sizes[10];

    cudaFuncSetAttribute(kGemm1MMA, cudaFuncAttributeMaxDynamicSharedMemorySize, SM1_TOTAL);
    cudaFuncSetAttribute(kGemm2MMA, cudaFuncAttributeMaxDynamicSharedMemorySize, SM2_TOTAL);

    kPre1<<<801, 256>>>(gamma, beta, phiw, P, toep, Wq, Kc);
    kEg<<<17, 256>>>(dlt);
    kApCab<<<384, 256>>>(P, gamma);
    kGemm1MMA<<<256, 256, SM1_TOTAL>>>(x, gamma);
    kScale<<<256, 256>>>(phib, glog, step, glen);
    kGemm2MMA<<<dim3(16, 128), 256, SM2_TOTAL>>>(bq, (float*)d_out);
}